// round 1
// baseline (speedup 1.0000x reference)
#include <cuda_runtime.h>
#include <cstddef>

// Problem constants
#define L_SEQ   2048
#define N_BATCH 2
#define E_DIM   1024
#define H_HEADS 16
#define D_HEAD  64
#define SCALE_F 0.125f                 // DH^-0.5 = 1/8
#define ROWS_TOT (L_SEQ * N_BATCH)     // 4096
#define F3       (3 * E_DIM)           // 3072
#define QKV_ROW  (N_BATCH * F3)        // 6144 floats per l in qkv buffer

// Scratch (no cudaMalloc allowed)
__device__ float g_qkv [(size_t)ROWS_TOT * F3];     // [L*N][3E]
__device__ float g_attn[(size_t)ROWS_TOT * E_DIM];  // [L*N][E]

// ---------------------------------------------------------------------------
// Generic NT SGEMM: C[M][Nc] = A[M][K] * B[Nc][K]^T   (all row-major, K contig)
// 128x128x16 tile, 256 threads, 8x8 per thread.
// Requires M,Nc % 128 == 0, K % 16 == 0 (true for all call sites).
// ---------------------------------------------------------------------------
__global__ __launch_bounds__(256) void gemm_nt(const float* __restrict__ A,
                                               const float* __restrict__ B,
                                               float* __restrict__ C,
                                               int M, int Nc, int K)
{
    __shared__ float As[16][132];   // transposed: As[k][m], pad to 132 (16B-mult rows)
    __shared__ float Bs[16][132];

    const int tid = threadIdx.x;
    const int tx = tid & 15;        // 0..15 -> N dim
    const int ty = tid >> 4;        // 0..15 -> M dim
    const int bm = blockIdx.y * 128;
    const int bn = blockIdx.x * 128;

    const int lr = tid >> 2;        // 0..63 tile row for loads
    const int lc = tid & 3;         // float4 column (k/4)

    const float* Ab = A + (size_t)bm * K;
    const float* Bb = B + (size_t)bn * K;

    float acc[8][8];
    #pragma unroll
    for (int i = 0; i < 8; i++)
        #pragma unroll
        for (int j = 0; j < 8; j++) acc[i][j] = 0.0f;

    for (int k0 = 0; k0 < K; k0 += 16) {
        #pragma unroll
        for (int s = 0; s < 2; s++) {
            int r = lr + s * 64;
            float4 va = *(const float4*)(Ab + (size_t)r * K + k0 + lc * 4);
            As[lc*4+0][r] = va.x; As[lc*4+1][r] = va.y;
            As[lc*4+2][r] = va.z; As[lc*4+3][r] = va.w;
            float4 vb = *(const float4*)(Bb + (size_t)r * K + k0 + lc * 4);
            Bs[lc*4+0][r] = vb.x; Bs[lc*4+1][r] = vb.y;
            Bs[lc*4+2][r] = vb.z; Bs[lc*4+3][r] = vb.w;
        }
        __syncthreads();

        #pragma unroll
        for (int kk = 0; kk < 16; kk++) {
            float a[8], b[8];
            *(float4*)(a)     = *(const float4*)&As[kk][ty*8];
            *(float4*)(a + 4) = *(const float4*)&As[kk][ty*8 + 4];
            *(float4*)(b)     = *(const float4*)&Bs[kk][tx*8];
            *(float4*)(b + 4) = *(const float4*)&Bs[kk][tx*8 + 4];
            #pragma unroll
            for (int i = 0; i < 8; i++)
                #pragma unroll
                for (int j = 0; j < 8; j++)
                    acc[i][j] += a[i] * b[j];
        }
        __syncthreads();
    }

    #pragma unroll
    for (int i = 0; i < 8; i++) {
        size_t r = (size_t)(bm + ty*8 + i);
        #pragma unroll
        for (int j = 0; j < 8; j += 4) {
            float4 v = make_float4(acc[i][j], acc[i][j+1], acc[i][j+2], acc[i][j+3]);
            *(float4*)(C + r * Nc + bn + tx*8 + j) = v;
        }
    }
}

// ---------------------------------------------------------------------------
// Flash attention (causal), fp32. One block per (q-tile of 64, head).
// 256 threads as 16(tx: cols/d) x 16(ty: rows), 4x4 micro-tile.
// All smem tiles: natural [row][col] layout, 64-float rows, XOR swizzle:
//   phys_col = col ^ (((row>>2)&7)<<3)   -> <=2-way on every access pattern.
// ---------------------------------------------------------------------------
#define SWZ(row) ((((row) >> 2) & 7) << 3)

__global__ __launch_bounds__(256) void flash_kernel(const float* __restrict__ qkv,
                                                    float* __restrict__ out)
{
    extern __shared__ float sm[];
    float* Qs = sm;                 // [64][64]
    float* Ks = sm + 64 * 64;
    float* Vs = sm + 2 * 64 * 64;
    float* Ps = sm + 3 * 64 * 64;

    const int tid = threadIdx.x;
    const int tx = tid & 15;
    const int ty = tid >> 4;
    const int qi = blockIdx.x;              // q tile 0..31
    const int b  = blockIdx.y;              // head 0..31
    const int n  = b >> 4;                  // b / H
    const int h  = b & 15;                  // b % H
    const int q0 = qi * 64;

    const int d4 = tid & 15;                // load mapping
    const int r0 = tid >> 4;                // 0..15

    const float* qbase = qkv + (size_t)n * F3 + h * D_HEAD;
    const float* kbase = qbase + E_DIM;
    const float* vbase = qbase + 2 * E_DIM;

    // Load Q tile (scaled)
    #pragma unroll
    for (int rr = r0; rr < 64; rr += 16) {
        float4 v = *(const float4*)(qbase + (size_t)(q0 + rr) * QKV_ROW + d4 * 4);
        v.x *= SCALE_F; v.y *= SCALE_F; v.z *= SCALE_F; v.w *= SCALE_F;
        *(float4*)&Qs[rr * 64 + ((d4 * 4) ^ SWZ(rr))] = v;
    }

    float m_i[4], l_i[4], acc[4][4];
    #pragma unroll
    for (int i = 0; i < 4; i++) {
        m_i[i] = -1e30f; l_i[i] = 0.0f;
        #pragma unroll
        for (int j = 0; j < 4; j++) acc[i][j] = 0.0f;
    }

    const int ta = (ty & 7) << 3;   // swizzle term for rows ty*4..ty*4+3
    const int tb = (tx & 7) << 3;   // swizzle term for rows tx*4..tx*4+3

    for (int kt = 0; kt <= qi; kt++) {
        __syncthreads();  // previous O-gemm done reading Ks/Vs
        const int k0r = kt * 64;
        #pragma unroll
        for (int rr = r0; rr < 64; rr += 16) {
            float4 vk = *(const float4*)(kbase + (size_t)(k0r + rr) * QKV_ROW + d4 * 4);
            *(float4*)&Ks[rr * 64 + ((d4 * 4) ^ SWZ(rr))] = vk;
            float4 vv = *(const float4*)(vbase + (size_t)(k0r + rr) * QKV_ROW + d4 * 4);
            *(float4*)&Vs[rr * 64 + ((d4 * 4) ^ SWZ(rr))] = vv;
        }
        __syncthreads();

        // S = Q @ K^T  (4x4 per thread)
        float s[4][4];
        #pragma unroll
        for (int i = 0; i < 4; i++)
            #pragma unroll
            for (int j = 0; j < 4; j++) s[i][j] = 0.0f;

        #pragma unroll
        for (int d0 = 0; d0 < 64; d0 += 4) {
            float4 av[4], bv[4];
            #pragma unroll
            for (int i = 0; i < 4; i++)
                av[i] = *(const float4*)&Qs[(ty*4 + i) * 64 + (d0 ^ ta)];
            #pragma unroll
            for (int j = 0; j < 4; j++)
                bv[j] = *(const float4*)&Ks[(tx*4 + j) * 64 + (d0 ^ tb)];
            #pragma unroll
            for (int i = 0; i < 4; i++)
                #pragma unroll
                for (int j = 0; j < 4; j++)
                    s[i][j] += av[i].x*bv[j].x + av[i].y*bv[j].y
                             + av[i].z*bv[j].z + av[i].w*bv[j].w;
        }

        // Causal mask on diagonal tile
        if (kt == qi) {
            #pragma unroll
            for (int i = 0; i < 4; i++)
                #pragma unroll
                for (int j = 0; j < 4; j++)
                    if (tx*4 + j > ty*4 + i) s[i][j] = -1e30f;
        }

        // Online softmax per owned row; store P (row-major, swizzled)
        #pragma unroll
        for (int i = 0; i < 4; i++) {
            float mx = fmaxf(fmaxf(s[i][0], s[i][1]), fmaxf(s[i][2], s[i][3]));
            #pragma unroll
            for (int o = 8; o > 0; o >>= 1)
                mx = fmaxf(mx, __shfl_xor_sync(0xffffffffu, mx, o));
            float m_new = fmaxf(m_i[i], mx);
            float alpha = __expf(m_i[i] - m_new);
            m_i[i] = m_new;
            float rs = 0.0f;
            #pragma unroll
            for (int j = 0; j < 4; j++) {
                s[i][j] = __expf(s[i][j] - m_new);
                rs += s[i][j];
            }
            #pragma unroll
            for (int o = 8; o > 0; o >>= 1)
                rs += __shfl_xor_sync(0xffffffffu, rs, o);
            l_i[i] = l_i[i] * alpha + rs;
            #pragma unroll
            for (int j = 0; j < 4; j++) acc[i][j] *= alpha;
            *(float4*)&Ps[(ty*4 + i) * 64 + ((tx*4) ^ ta)] =
                make_float4(s[i][0], s[i][1], s[i][2], s[i][3]);
        }
        __syncthreads();

        // O += P @ V
        #pragma unroll
        for (int j0 = 0; j0 < 64; j0 += 4) {
            float4 av[4], bv[4];
            #pragma unroll
            for (int i = 0; i < 4; i++)
                av[i] = *(const float4*)&Ps[(ty*4 + i) * 64 + (j0 ^ ta)];
            const int tv = SWZ(j0);
            #pragma unroll
            for (int s2 = 0; s2 < 4; s2++)
                bv[s2] = *(const float4*)&Vs[(j0 + s2) * 64 + ((tx*4) ^ tv)];
            #pragma unroll
            for (int i = 0; i < 4; i++) {
                acc[i][0] += av[i].x*bv[0].x + av[i].y*bv[1].x + av[i].z*bv[2].x + av[i].w*bv[3].x;
                acc[i][1] += av[i].x*bv[0].y + av[i].y*bv[1].y + av[i].z*bv[2].y + av[i].w*bv[3].y;
                acc[i][2] += av[i].x*bv[0].z + av[i].y*bv[1].z + av[i].z*bv[2].z + av[i].w*bv[3].z;
                acc[i][3] += av[i].x*bv[0].w + av[i].y*bv[1].w + av[i].z*bv[2].w + av[i].w*bv[3].w;
            }
        }
    }

    // Epilogue: normalize and write to attn buffer [L*N][E]
    #pragma unroll
    for (int i = 0; i < 4; i++) {
        int l = q0 + ty*4 + i;
        float inv = 1.0f / l_i[i];
        float4 v = make_float4(acc[i][0]*inv, acc[i][1]*inv, acc[i][2]*inv, acc[i][3]*inv);
        *(float4*)&out[((size_t)l * N_BATCH + n) * E_DIM + h * D_HEAD + tx*4] = v;
    }
}

// ---------------------------------------------------------------------------
extern "C" void kernel_launch(void* const* d_in, const int* in_sizes, int n_in,
                              void* d_out, int out_size)
{
    const float* x     = (const float*)d_in[0];   // [L,N,E]
    const float* w_qkv = (const float*)d_in[1];   // [3E,E]
    const float* w_out = (const float*)d_in[2];   // [E,E]
    float* out = (float*)d_out;                   // [L,N,E]

    float *qkv, *attn;
    cudaGetSymbolAddress((void**)&qkv,  g_qkv);
    cudaGetSymbolAddress((void**)&attn, g_attn);
    cudaFuncSetAttribute(flash_kernel,
                         cudaFuncAttributeMaxDynamicSharedMemorySize, 64 * 1024);

    // 1) QKV projection
    gemm_nt<<<dim3(F3 / 128, ROWS_TOT / 128), 256>>>(x, w_qkv, qkv,
                                                     ROWS_TOT, F3, E_DIM);
    // 2) Causal flash attention, 32 heads
    flash_kernel<<<dim3(L_SEQ / 64, N_BATCH * H_HEADS), 256, 64 * 1024>>>(qkv, attn);
    // 3) Output projection
    gemm_nt<<<dim3(E_DIM / 128, ROWS_TOT / 128), 256>>>(attn, w_out, out,
                                                        ROWS_TOT, E_DIM, E_DIM);
}

// round 3
// speedup vs baseline: 1.3865x; 1.3865x over previous
#include <cuda_runtime.h>
#include <cuda_bf16.h>
#include <cstdint>
#include <cstddef>

// Problem constants
#define L_SEQ   2048
#define N_BATCH 2
#define E_DIM   1024
#define H_HEADS 16
#define D_HEAD  64
#define SCALE_F 0.125f
#define ROWS_TOT (L_SEQ * N_BATCH)     // 4096
#define F3       (3 * E_DIM)           // 3072
#define QKV_ROW  (N_BATCH * F3)        // 6144

// ---------------------------------------------------------------------------
// Scratch (no cudaMalloc allowed)
// ---------------------------------------------------------------------------
__device__ float g_qkv [(size_t)ROWS_TOT * F3];
__device__ float g_attn[(size_t)ROWS_TOT * E_DIM];
__device__ __nv_bfloat16 g_xh [(size_t)ROWS_TOT * E_DIM];
__device__ __nv_bfloat16 g_xl [(size_t)ROWS_TOT * E_DIM];
__device__ __nv_bfloat16 g_wqh[(size_t)F3 * E_DIM];
__device__ __nv_bfloat16 g_wql[(size_t)F3 * E_DIM];
__device__ __nv_bfloat16 g_woh[(size_t)E_DIM * E_DIM];
__device__ __nv_bfloat16 g_wol[(size_t)E_DIM * E_DIM];
__device__ __nv_bfloat16 g_ah [(size_t)ROWS_TOT * E_DIM];
__device__ __nv_bfloat16 g_al [(size_t)ROWS_TOT * E_DIM];

// ---------------------------------------------------------------------------
// Helpers
// ---------------------------------------------------------------------------
__device__ __forceinline__ uint32_t smem_u32(const void* p) {
    uint32_t a;
    asm("{ .reg .u64 t; cvta.to.shared.u64 t, %1; cvt.u32.u64 %0, t; }"
        : "=r"(a) : "l"(p));
    return a;
}

__device__ __forceinline__ void cp_async16(uint32_t dst, const void* src) {
    asm volatile("cp.async.cg.shared.global [%0], [%1], 16;"
                 :: "r"(dst), "l"(src) : "memory");
}
#define CP_COMMIT()  asm volatile("cp.async.commit_group;" ::: "memory")
#define CP_WAIT(n)   asm volatile("cp.async.wait_group %0;" :: "n"(n) : "memory")

__device__ __forceinline__ void mma16816(float* d, const uint32_t* a,
                                         const uint32_t* b) {
    asm volatile(
        "mma.sync.aligned.m16n8k16.row.col.f32.bf16.bf16.f32 "
        "{%0,%1,%2,%3}, {%4,%5,%6,%7}, {%8,%9}, {%0,%1,%2,%3};"
        : "+f"(d[0]), "+f"(d[1]), "+f"(d[2]), "+f"(d[3])
        : "r"(a[0]), "r"(a[1]), "r"(a[2]), "r"(a[3]), "r"(b[0]), "r"(b[1]));
}

// ---------------------------------------------------------------------------
// Split conversion: x -> (hi, lo) bf16 pair
// ---------------------------------------------------------------------------
__global__ void convert_split(const float* __restrict__ x,
                              __nv_bfloat16* __restrict__ hi,
                              __nv_bfloat16* __restrict__ lo, int n4)
{
    int i = blockIdx.x * blockDim.x + threadIdx.x;
    if (i >= n4) return;
    float4 v = *(const float4*)(x + (size_t)i * 4);
    __nv_bfloat16 h[4], l[4];
    float vv[4] = {v.x, v.y, v.z, v.w};
    #pragma unroll
    for (int k = 0; k < 4; k++) {
        h[k] = __float2bfloat16_rn(vv[k]);
        l[k] = __float2bfloat16_rn(vv[k] - __bfloat162float(h[k]));
    }
    *(uint2*)(hi + (size_t)i * 4) = *(uint2*)h;
    *(uint2*)(lo + (size_t)i * 4) = *(uint2*)l;
}

// ---------------------------------------------------------------------------
// Split-bf16 NT GEMM on mma.sync: C[M][Nc] = A[M][K] * B[Nc][K]^T
// 128x128x32 CTA tile, 8 warps (2Mx4N), warp tile 64x32, 2-stage cp.async.
// ---------------------------------------------------------------------------
#define BK    32
#define PADK  40                                // row stride in bf16 elems
#define TILE_BYTES  (128 * PADK * 2)            // 10240
#define STAGE_BYTES (4 * TILE_BYTES)            // 40960 (Ah, Al, Bh, Bl)
#define GEMM_SMEM   (2 * STAGE_BYTES)           // 81920

__global__ __launch_bounds__(256, 1) void gemm_mma(
    const __nv_bfloat16* __restrict__ Ah, const __nv_bfloat16* __restrict__ Al,
    const __nv_bfloat16* __restrict__ Bh, const __nv_bfloat16* __restrict__ Bl,
    float* __restrict__ C, int M, int Nc, int K)
{
    extern __shared__ __align__(16) char smem[];
    const int tid  = threadIdx.x;
    const int lane = tid & 31;
    const int wid  = tid >> 5;
    const int bm = blockIdx.y * 128;
    const int bn = blockIdx.x * 128;
    const int wm = (wid >> 2) * 64;     // warp M offset in tile
    const int wn = (wid & 3) * 32;      // warp N offset

    const __nv_bfloat16* gsrc[4] = {
        Ah + (size_t)bm * K, Al + (size_t)bm * K,
        Bh + (size_t)bn * K, Bl + (size_t)bn * K };

    // Loader mapping: thread -> (row = tid/4 + it*64, 16B chunk = tid%4)
    const int lrow = tid >> 2;
    const int lcb  = (tid & 3) * 8;     // col in elems

    auto load_stage = [&](int stage, int c) {
        const int k0 = c * BK;
        #pragma unroll
        for (int t = 0; t < 4; t++) {
            __nv_bfloat16* dst =
                (__nv_bfloat16*)(smem + stage * STAGE_BYTES + t * TILE_BYTES);
            #pragma unroll
            for (int it = 0; it < 2; it++) {
                const int r = lrow + it * 64;
                cp_async16(smem_u32(dst + r * PADK + lcb),
                           gsrc[t] + (size_t)r * K + k0 + lcb);
            }
        }
        CP_COMMIT();
    };

    float d[4][4][4];
    #pragma unroll
    for (int i = 0; i < 4; i++)
        #pragma unroll
        for (int j = 0; j < 4; j++)
            #pragma unroll
            for (int r = 0; r < 4; r++) d[i][j][r] = 0.0f;

    const int lr4 = lane >> 2;          // 0..7
    const int lk2 = (lane & 3) * 2;     // 0,2,4,6

    const int nch = K / BK;
    load_stage(0, 0);

    for (int c = 0; c < nch; c++) {
        const int sg = c & 1;
        if (c + 1 < nch) {
            load_stage((c + 1) & 1, c + 1);
            CP_WAIT(1);
        } else {
            CP_WAIT(0);
        }
        __syncthreads();

        const __nv_bfloat16* Ash =
            (const __nv_bfloat16*)(smem + sg * STAGE_BYTES);
        const __nv_bfloat16* Asl = Ash + 128 * PADK;
        const __nv_bfloat16* Bsh = Asl + 128 * PADK;
        const __nv_bfloat16* Bsl = Bsh + 128 * PADK;

        #pragma unroll
        for (int s = 0; s < 2; s++) {           // two k16 steps
            const int kb = s * 16 + lk2;
            uint32_t afh[4][4], afl[4][4], bfh[4][2], bfl[4][2];
            #pragma unroll
            for (int i = 0; i < 4; i++) {
                const int r = wm + i * 16 + lr4;
                afh[i][0] = *(const uint32_t*)(Ash + r * PADK + kb);
                afh[i][1] = *(const uint32_t*)(Ash + (r + 8) * PADK + kb);
                afh[i][2] = *(const uint32_t*)(Ash + r * PADK + kb + 8);
                afh[i][3] = *(const uint32_t*)(Ash + (r + 8) * PADK + kb + 8);
                afl[i][0] = *(const uint32_t*)(Asl + r * PADK + kb);
                afl[i][1] = *(const uint32_t*)(Asl + (r + 8) * PADK + kb);
                afl[i][2] = *(const uint32_t*)(Asl + r * PADK + kb + 8);
                afl[i][3] = *(const uint32_t*)(Asl + (r + 8) * PADK + kb + 8);
            }
            #pragma unroll
            for (int j = 0; j < 4; j++) {
                const int n = wn + j * 8 + lr4;
                bfh[j][0] = *(const uint32_t*)(Bsh + n * PADK + kb);
                bfh[j][1] = *(const uint32_t*)(Bsh + n * PADK + kb + 8);
                bfl[j][0] = *(const uint32_t*)(Bsl + n * PADK + kb);
                bfl[j][1] = *(const uint32_t*)(Bsl + n * PADK + kb + 8);
            }
            #pragma unroll
            for (int i = 0; i < 4; i++)
                #pragma unroll
                for (int j = 0; j < 4; j++) {
                    mma16816(d[i][j], afh[i], bfh[j]);
                    mma16816(d[i][j], afh[i], bfl[j]);
                    mma16816(d[i][j], afl[i], bfh[j]);
                }
        }
        __syncthreads();
    }

    // Epilogue: c0,c1 at (row, col), c2,c3 at (row+8, col)
    #pragma unroll
    for (int i = 0; i < 4; i++) {
        const int row = bm + wm + i * 16 + lr4;
        #pragma unroll
        for (int j = 0; j < 4; j++) {
            const int col = bn + wn + j * 8 + lk2;
            *(float2*)(C + (size_t)row * Nc + col) =
                make_float2(d[i][j][0], d[i][j][1]);
            *(float2*)(C + (size_t)(row + 8) * Nc + col) =
                make_float2(d[i][j][2], d[i][j][3]);
        }
    }
}

// ---------------------------------------------------------------------------
// Flash attention (causal), fp32 — unchanged (known good).
// ---------------------------------------------------------------------------
#define SWZ(row) ((((row) >> 2) & 7) << 3)

__global__ __launch_bounds__(256) void flash_kernel(const float* __restrict__ qkv,
                                                    float* __restrict__ out)
{
    extern __shared__ float sm[];
    float* Qs = sm;
    float* Ks = sm + 64 * 64;
    float* Vs = sm + 2 * 64 * 64;
    float* Ps = sm + 3 * 64 * 64;

    const int tid = threadIdx.x;
    const int tx = tid & 15;
    const int ty = tid >> 4;
    const int qi = blockIdx.x;
    const int b  = blockIdx.y;
    const int n  = b >> 4;
    const int h  = b & 15;
    const int q0 = qi * 64;

    const int d4 = tid & 15;
    const int r0 = tid >> 4;

    const float* qbase = qkv + (size_t)n * F3 + h * D_HEAD;
    const float* kbase = qbase + E_DIM;
    const float* vbase = qbase + 2 * E_DIM;

    #pragma unroll
    for (int rr = r0; rr < 64; rr += 16) {
        float4 v = *(const float4*)(qbase + (size_t)(q0 + rr) * QKV_ROW + d4 * 4);
        v.x *= SCALE_F; v.y *= SCALE_F; v.z *= SCALE_F; v.w *= SCALE_F;
        *(float4*)&Qs[rr * 64 + ((d4 * 4) ^ SWZ(rr))] = v;
    }

    float m_i[4], l_i[4], acc[4][4];
    #pragma unroll
    for (int i = 0; i < 4; i++) {
        m_i[i] = -1e30f; l_i[i] = 0.0f;
        #pragma unroll
        for (int j = 0; j < 4; j++) acc[i][j] = 0.0f;
    }

    const int ta = (ty & 7) << 3;
    const int tb = (tx & 7) << 3;

    for (int kt = 0; kt <= qi; kt++) {
        __syncthreads();
        const int k0r = kt * 64;
        #pragma unroll
        for (int rr = r0; rr < 64; rr += 16) {
            float4 vk = *(const float4*)(kbase + (size_t)(k0r + rr) * QKV_ROW + d4 * 4);
            *(float4*)&Ks[rr * 64 + ((d4 * 4) ^ SWZ(rr))] = vk;
            float4 vv = *(const float4*)(vbase + (size_t)(k0r + rr) * QKV_ROW + d4 * 4);
            *(float4*)&Vs[rr * 64 + ((d4 * 4) ^ SWZ(rr))] = vv;
        }
        __syncthreads();

        float s[4][4];
        #pragma unroll
        for (int i = 0; i < 4; i++)
            #pragma unroll
            for (int j = 0; j < 4; j++) s[i][j] = 0.0f;

        #pragma unroll
        for (int d0 = 0; d0 < 64; d0 += 4) {
            float4 av[4], bv[4];
            #pragma unroll
            for (int i = 0; i < 4; i++)
                av[i] = *(const float4*)&Qs[(ty*4 + i) * 64 + (d0 ^ ta)];
            #pragma unroll
            for (int j = 0; j < 4; j++)
                bv[j] = *(const float4*)&Ks[(tx*4 + j) * 64 + (d0 ^ tb)];
            #pragma unroll
            for (int i = 0; i < 4; i++)
                #pragma unroll
                for (int j = 0; j < 4; j++)
                    s[i][j] += av[i].x*bv[j].x + av[i].y*bv[j].y
                             + av[i].z*bv[j].z + av[i].w*bv[j].w;
        }

        if (kt == qi) {
            #pragma unroll
            for (int i = 0; i < 4; i++)
                #pragma unroll
                for (int j = 0; j < 4; j++)
                    if (tx*4 + j > ty*4 + i) s[i][j] = -1e30f;
        }

        #pragma unroll
        for (int i = 0; i < 4; i++) {
            float mx = fmaxf(fmaxf(s[i][0], s[i][1]), fmaxf(s[i][2], s[i][3]));
            #pragma unroll
            for (int o = 8; o > 0; o >>= 1)
                mx = fmaxf(mx, __shfl_xor_sync(0xffffffffu, mx, o));
            float m_new = fmaxf(m_i[i], mx);
            float alpha = __expf(m_i[i] - m_new);
            m_i[i] = m_new;
            float rs = 0.0f;
            #pragma unroll
            for (int j = 0; j < 4; j++) {
                s[i][j] = __expf(s[i][j] - m_new);
                rs += s[i][j];
            }
            #pragma unroll
            for (int o = 8; o > 0; o >>= 1)
                rs += __shfl_xor_sync(0xffffffffu, rs, o);
            l_i[i] = l_i[i] * alpha + rs;
            #pragma unroll
            for (int j = 0; j < 4; j++) acc[i][j] *= alpha;
            *(float4*)&Ps[(ty*4 + i) * 64 + ((tx*4) ^ ta)] =
                make_float4(s[i][0], s[i][1], s[i][2], s[i][3]);
        }
        __syncthreads();

        #pragma unroll
        for (int j0 = 0; j0 < 64; j0 += 4) {
            float4 av[4], bv[4];
            #pragma unroll
            for (int i = 0; i < 4; i++)
                av[i] = *(const float4*)&Ps[(ty*4 + i) * 64 + (j0 ^ ta)];
            const int tv = SWZ(j0);
            #pragma unroll
            for (int s2 = 0; s2 < 4; s2++)
                bv[s2] = *(const float4*)&Vs[(j0 + s2) * 64 + ((tx*4) ^ tv)];
            #pragma unroll
            for (int i = 0; i < 4; i++) {
                acc[i][0] += av[i].x*bv[0].x + av[i].y*bv[1].x + av[i].z*bv[2].x + av[i].w*bv[3].x;
                acc[i][1] += av[i].x*bv[0].y + av[i].y*bv[1].y + av[i].z*bv[2].y + av[i].w*bv[3].y;
                acc[i][2] += av[i].x*bv[0].z + av[i].y*bv[1].z + av[i].z*bv[2].z + av[i].w*bv[3].z;
                acc[i][3] += av[i].x*bv[0].w + av[i].y*bv[1].w + av[i].z*bv[2].w + av[i].w*bv[3].w;
            }
        }
    }

    #pragma unroll
    for (int i = 0; i < 4; i++) {
        int l = q0 + ty*4 + i;
        float inv = 1.0f / l_i[i];
        float4 v = make_float4(acc[i][0]*inv, acc[i][1]*inv, acc[i][2]*inv, acc[i][3]*inv);
        *(float4*)&out[((size_t)l * N_BATCH + n) * E_DIM + h * D_HEAD + tx*4] = v;
    }
}

// ---------------------------------------------------------------------------
extern "C" void kernel_launch(void* const* d_in, const int* in_sizes, int n_in,
                              void* d_out, int out_size)
{
    const float* x     = (const float*)d_in[0];
    const float* w_qkv = (const float*)d_in[1];
    const float* w_out = (const float*)d_in[2];
    float* out = (float*)d_out;

    float *qkv, *attn;
    __nv_bfloat16 *xh, *xl, *wqh, *wql, *woh, *wol, *ah, *al;
    cudaGetSymbolAddress((void**)&qkv,  g_qkv);
    cudaGetSymbolAddress((void**)&attn, g_attn);
    cudaGetSymbolAddress((void**)&xh,   g_xh);
    cudaGetSymbolAddress((void**)&xl,   g_xl);
    cudaGetSymbolAddress((void**)&wqh,  g_wqh);
    cudaGetSymbolAddress((void**)&wql,  g_wql);
    cudaGetSymbolAddress((void**)&woh,  g_woh);
    cudaGetSymbolAddress((void**)&wol,  g_wol);
    cudaGetSymbolAddress((void**)&ah,   g_ah);
    cudaGetSymbolAddress((void**)&al,   g_al);

    cudaFuncSetAttribute(gemm_mma,
                         cudaFuncAttributeMaxDynamicSharedMemorySize, GEMM_SMEM);
    cudaFuncSetAttribute(flash_kernel,
                         cudaFuncAttributeMaxDynamicSharedMemorySize, 64 * 1024);

    // 0) split conversions
    {
        int n4 = ROWS_TOT * E_DIM / 4;
        convert_split<<<(n4 + 255) / 256, 256>>>(x, xh, xl, n4);
        n4 = F3 * E_DIM / 4;
        convert_split<<<(n4 + 255) / 256, 256>>>(w_qkv, wqh, wql, n4);
        n4 = E_DIM * E_DIM / 4;
        convert_split<<<(n4 + 255) / 256, 256>>>(w_out, woh, wol, n4);
    }

    // 1) QKV projection (tensor cores via mma.sync)
    gemm_mma<<<dim3(F3 / 128, ROWS_TOT / 128), 256, GEMM_SMEM>>>(
        xh, xl, wqh, wql, qkv, ROWS_TOT, F3, E_DIM);

    // 2) Causal flash attention (fp32 SIMT)
    flash_kernel<<<dim3(L_SEQ / 64, N_BATCH * H_HEADS), 256, 64 * 1024>>>(qkv, attn);

    // 3) split-convert attention output, then output projection
    {
        int n4 = ROWS_TOT * E_DIM / 4;
        convert_split<<<(n4 + 255) / 256, 256>>>(attn, ah, al, n4);
    }
    gemm_mma<<<dim3(E_DIM / 128, ROWS_TOT / 128), 256, GEMM_SMEM>>>(
        ah, al, woh, wol, out, ROWS_TOT, E_DIM, E_DIM);
}

// round 4
// speedup vs baseline: 2.4211x; 1.7461x over previous
#include <cuda_runtime.h>
#include <cuda_bf16.h>
#include <cstdint>
#include <cstddef>

// Problem constants
#define L_SEQ   2048
#define N_BATCH 2
#define E_DIM   1024
#define H_HEADS 16
#define D_HEAD  64
#define SCALE_F 0.125f
#define ROWS_TOT (L_SEQ * N_BATCH)     // 4096
#define F3       (3 * E_DIM)           // 3072
#define QKV_ROW  (N_BATCH * F3)        // 6144

// ---------------------------------------------------------------------------
// Scratch (no cudaMalloc allowed)
// ---------------------------------------------------------------------------
__device__ float g_qkv [(size_t)ROWS_TOT * F3];
__device__ __nv_bfloat16 g_xh [(size_t)ROWS_TOT * E_DIM];
__device__ __nv_bfloat16 g_xl [(size_t)ROWS_TOT * E_DIM];
__device__ __nv_bfloat16 g_wqh[(size_t)F3 * E_DIM];
__device__ __nv_bfloat16 g_wql[(size_t)F3 * E_DIM];
__device__ __nv_bfloat16 g_woh[(size_t)E_DIM * E_DIM];
__device__ __nv_bfloat16 g_wol[(size_t)E_DIM * E_DIM];
__device__ __nv_bfloat16 g_ah [(size_t)ROWS_TOT * E_DIM];
__device__ __nv_bfloat16 g_al [(size_t)ROWS_TOT * E_DIM];

// ---------------------------------------------------------------------------
// Helpers
// ---------------------------------------------------------------------------
__device__ __forceinline__ uint32_t smem_u32(const void* p) {
    uint32_t a;
    asm("{ .reg .u64 t; cvta.to.shared.u64 t, %1; cvt.u32.u64 %0, t; }"
        : "=r"(a) : "l"(p));
    return a;
}

__device__ __forceinline__ void cp_async16(uint32_t dst, const void* src) {
    asm volatile("cp.async.cg.shared.global [%0], [%1], 16;"
                 :: "r"(dst), "l"(src) : "memory");
}
#define CP_COMMIT()  asm volatile("cp.async.commit_group;" ::: "memory")
#define CP_WAIT(n)   asm volatile("cp.async.wait_group %0;" :: "n"(n) : "memory")

__device__ __forceinline__ void mma16816(float* d, const uint32_t* a,
                                         const uint32_t* b) {
    asm volatile(
        "mma.sync.aligned.m16n8k16.row.col.f32.bf16.bf16.f32 "
        "{%0,%1,%2,%3}, {%4,%5,%6,%7}, {%8,%9}, {%0,%1,%2,%3};"
        : "+f"(d[0]), "+f"(d[1]), "+f"(d[2]), "+f"(d[3])
        : "r"(a[0]), "r"(a[1]), "r"(a[2]), "r"(a[3]), "r"(b[0]), "r"(b[1]));
}

__device__ __forceinline__ void ldmx2t(uint32_t addr, uint32_t* r) {
    asm volatile("ldmatrix.sync.aligned.m8n8.x2.trans.shared.b16 {%0,%1}, [%2];"
                 : "=r"(r[0]), "=r"(r[1]) : "r"(addr));
}

// split a pair of fp32 into packed bf16 hi and bf16 lo (residual)
__device__ __forceinline__ void split2(float a, float b, uint32_t& hi, uint32_t& lo) {
    __nv_bfloat162 h = __floats2bfloat162_rn(a, b);
    float ra = a - __bfloat162float(h.x);
    float rb = b - __bfloat162float(h.y);
    __nv_bfloat162 l2 = __floats2bfloat162_rn(ra, rb);
    hi = *(uint32_t*)&h;
    lo = *(uint32_t*)&l2;
}

// ---------------------------------------------------------------------------
// Split conversion kernel (inputs)
// ---------------------------------------------------------------------------
__global__ void convert_split(const float* __restrict__ x,
                              __nv_bfloat16* __restrict__ hi,
                              __nv_bfloat16* __restrict__ lo, int n4)
{
    int i = blockIdx.x * blockDim.x + threadIdx.x;
    if (i >= n4) return;
    float4 v = *(const float4*)(x + (size_t)i * 4);
    uint32_t h0, l0, h1, l1;
    split2(v.x, v.y, h0, l0);
    split2(v.z, v.w, h1, l1);
    *(uint2*)(hi + (size_t)i * 4) = make_uint2(h0, h1);
    *(uint2*)(lo + (size_t)i * 4) = make_uint2(l0, l1);
}

// ---------------------------------------------------------------------------
// Split-bf16 NT GEMM on mma.sync (unchanged from R3 — validated)
// ---------------------------------------------------------------------------
#define BK    32
#define PADK  40
#define TILE_BYTES  (128 * PADK * 2)
#define STAGE_BYTES (4 * TILE_BYTES)
#define GEMM_SMEM   (2 * STAGE_BYTES)

__global__ __launch_bounds__(256, 1) void gemm_mma(
    const __nv_bfloat16* __restrict__ Ah, const __nv_bfloat16* __restrict__ Al,
    const __nv_bfloat16* __restrict__ Bh, const __nv_bfloat16* __restrict__ Bl,
    float* __restrict__ C, int M, int Nc, int K)
{
    extern __shared__ __align__(16) char smem[];
    const int tid  = threadIdx.x;
    const int lane = tid & 31;
    const int wid  = tid >> 5;
    const int bm = blockIdx.y * 128;
    const int bn = blockIdx.x * 128;
    const int wm = (wid >> 2) * 64;
    const int wn = (wid & 3) * 32;

    const __nv_bfloat16* gsrc[4] = {
        Ah + (size_t)bm * K, Al + (size_t)bm * K,
        Bh + (size_t)bn * K, Bl + (size_t)bn * K };

    const int lrow = tid >> 2;
    const int lcb  = (tid & 3) * 8;

    auto load_stage = [&](int stage, int c) {
        const int k0 = c * BK;
        #pragma unroll
        for (int t = 0; t < 4; t++) {
            __nv_bfloat16* dst =
                (__nv_bfloat16*)(smem + stage * STAGE_BYTES + t * TILE_BYTES);
            #pragma unroll
            for (int it = 0; it < 2; it++) {
                const int r = lrow + it * 64;
                cp_async16(smem_u32(dst + r * PADK + lcb),
                           gsrc[t] + (size_t)r * K + k0 + lcb);
            }
        }
        CP_COMMIT();
    };

    float d[4][4][4];
    #pragma unroll
    for (int i = 0; i < 4; i++)
        #pragma unroll
        for (int j = 0; j < 4; j++)
            #pragma unroll
            for (int r = 0; r < 4; r++) d[i][j][r] = 0.0f;

    const int lr4 = lane >> 2;
    const int lk2 = (lane & 3) * 2;

    const int nch = K / BK;
    load_stage(0, 0);

    for (int c = 0; c < nch; c++) {
        const int sg = c & 1;
        if (c + 1 < nch) {
            load_stage((c + 1) & 1, c + 1);
            CP_WAIT(1);
        } else {
            CP_WAIT(0);
        }
        __syncthreads();

        const __nv_bfloat16* Ash =
            (const __nv_bfloat16*)(smem + sg * STAGE_BYTES);
        const __nv_bfloat16* Asl = Ash + 128 * PADK;
        const __nv_bfloat16* Bsh = Asl + 128 * PADK;
        const __nv_bfloat16* Bsl = Bsh + 128 * PADK;

        #pragma unroll
        for (int s = 0; s < 2; s++) {
            const int kb = s * 16 + lk2;
            uint32_t afh[4][4], afl[4][4], bfh[4][2], bfl[4][2];
            #pragma unroll
            for (int i = 0; i < 4; i++) {
                const int r = wm + i * 16 + lr4;
                afh[i][0] = *(const uint32_t*)(Ash + r * PADK + kb);
                afh[i][1] = *(const uint32_t*)(Ash + (r + 8) * PADK + kb);
                afh[i][2] = *(const uint32_t*)(Ash + r * PADK + kb + 8);
                afh[i][3] = *(const uint32_t*)(Ash + (r + 8) * PADK + kb + 8);
                afl[i][0] = *(const uint32_t*)(Asl + r * PADK + kb);
                afl[i][1] = *(const uint32_t*)(Asl + (r + 8) * PADK + kb);
                afl[i][2] = *(const uint32_t*)(Asl + r * PADK + kb + 8);
                afl[i][3] = *(const uint32_t*)(Asl + (r + 8) * PADK + kb + 8);
            }
            #pragma unroll
            for (int j = 0; j < 4; j++) {
                const int n = wn + j * 8 + lr4;
                bfh[j][0] = *(const uint32_t*)(Bsh + n * PADK + kb);
                bfh[j][1] = *(const uint32_t*)(Bsh + n * PADK + kb + 8);
                bfl[j][0] = *(const uint32_t*)(Bsl + n * PADK + kb);
                bfl[j][1] = *(const uint32_t*)(Bsl + n * PADK + kb + 8);
            }
            #pragma unroll
            for (int i = 0; i < 4; i++)
                #pragma unroll
                for (int j = 0; j < 4; j++) {
                    mma16816(d[i][j], afh[i], bfh[j]);
                    mma16816(d[i][j], afh[i], bfl[j]);
                    mma16816(d[i][j], afl[i], bfh[j]);
                }
        }
        __syncthreads();
    }

    #pragma unroll
    for (int i = 0; i < 4; i++) {
        const int row = bm + wm + i * 16 + lr4;
        #pragma unroll
        for (int j = 0; j < 4; j++) {
            const int col = bn + wn + j * 8 + lk2;
            *(float2*)(C + (size_t)row * Nc + col) =
                make_float2(d[i][j][0], d[i][j][1]);
            *(float2*)(C + (size_t)(row + 8) * Nc + col) =
                make_float2(d[i][j][2], d[i][j][3]);
        }
    }
}

// ---------------------------------------------------------------------------
// Flash attention on mma.sync, split-bf16, causal.
// Block = (128 q rows, one head). 8 warps, each m16 rows. K/V tile = 64.
// Writes hi/lo bf16 split of O directly to g_ah/g_al.
// ---------------------------------------------------------------------------
#define FPAD 72     // bf16 row stride for 64-wide K/V tiles (16B-aligned rows)

__global__ __launch_bounds__(256) void flash_mma(
    const float* __restrict__ qkv,
    __nv_bfloat16* __restrict__ ah, __nv_bfloat16* __restrict__ al)
{
    __shared__ __align__(16) char fsm[4 * 64 * FPAD * 2];   // 36864 B
    float* Qst = (float*)fsm;                               // [128][68] (phase 1)
    __nv_bfloat16* Kh = (__nv_bfloat16*)fsm;                // [64][FPAD]
    __nv_bfloat16* Kl = Kh + 64 * FPAD;
    __nv_bfloat16* Vh = Kl + 64 * FPAD;
    __nv_bfloat16* Vl = Vh + 64 * FPAD;

    const int tid  = threadIdx.x;
    const int lane = tid & 31;
    const int w    = tid >> 5;
    const int qi   = (int)gridDim.x - 1 - (int)blockIdx.x;  // heavy blocks first
    const int by   = blockIdx.y;
    const int n    = by >> 4;
    const int h    = by & 15;
    const int q0   = qi * 128;
    const int lr4  = lane >> 2;
    const int lk2  = (lane & 3) * 2;

    const float* qb  = qkv + (size_t)n * F3 + h * D_HEAD;
    const float* kbp = qb + E_DIM;
    const float* vbp = qb + 2 * E_DIM;

    // ---- Phase 1: stage Q (scaled) to smem, build per-warp Q fragments ----
    #pragma unroll
    for (int i = 0; i < 8; i++) {
        int ch = tid + i * 256;             // 2048 float4 chunks
        int r  = ch >> 4;
        int c  = (ch & 15) * 4;
        float4 v = *(const float4*)(qb + (size_t)(q0 + r) * QKV_ROW + c);
        float* dst = Qst + r * 68 + c;
        dst[0] = v.x * SCALE_F; dst[1] = v.y * SCALE_F;
        dst[2] = v.z * SCALE_F; dst[3] = v.w * SCALE_F;
    }
    __syncthreads();

    uint32_t qh[4][4], ql[4][4];
    {
        const int rq = w * 16 + lr4;
        #pragma unroll
        for (int s = 0; s < 4; s++) {
            const int k0 = s * 16 + lk2;
            const float* r0p = Qst + rq * 68;
            const float* r1p = Qst + (rq + 8) * 68;
            split2(r0p[k0],     r0p[k0 + 1], qh[s][0], ql[s][0]);
            split2(r1p[k0],     r1p[k0 + 1], qh[s][1], ql[s][1]);
            split2(r0p[k0 + 8], r0p[k0 + 9], qh[s][2], ql[s][2]);
            split2(r1p[k0 + 8], r1p[k0 + 9], qh[s][3], ql[s][3]);
        }
    }

    // ---- Online softmax state ----
    float rm0 = -1e30f, rm1 = -1e30f, rl0 = 0.0f, rl1 = 0.0f;
    float o[8][4];
    #pragma unroll
    for (int j = 0; j < 8; j++)
        #pragma unroll
        for (int r = 0; r < 4; r++) o[j][r] = 0.0f;

    const int nkt = 2 * qi + 2;
    for (int kt = 0; kt < nkt; kt++) {
        __syncthreads();   // smem free (prev iter / Q-frag phase done)

        // ---- load + split K,V tiles ----
        #pragma unroll
        for (int i = 0; i < 4; i++) {
            int ch = tid + i * 256;         // 1024 chunks
            int r  = ch >> 4;
            int c  = (ch & 15) * 4;
            size_t go = (size_t)(kt * 64 + r) * QKV_ROW + c;
            float4 vk = *(const float4*)(kbp + go);
            float4 vv = *(const float4*)(vbp + go);
            uint32_t h0, l0u, h1, l1u;
            split2(vk.x, vk.y, h0, l0u); split2(vk.z, vk.w, h1, l1u);
            *(uint2*)(Kh + r * FPAD + c) = make_uint2(h0, h1);
            *(uint2*)(Kl + r * FPAD + c) = make_uint2(l0u, l1u);
            split2(vv.x, vv.y, h0, l0u); split2(vv.z, vv.w, h1, l1u);
            *(uint2*)(Vh + r * FPAD + c) = make_uint2(h0, h1);
            *(uint2*)(Vl + r * FPAD + c) = make_uint2(l0u, l1u);
        }
        __syncthreads();

        // ---- S = Q K^T (split, 3 terms) ----
        float s[8][4];
        #pragma unroll
        for (int j = 0; j < 8; j++)
            #pragma unroll
            for (int r = 0; r < 4; r++) s[j][r] = 0.0f;

        #pragma unroll
        for (int st = 0; st < 4; st++) {
            const int kb = st * 16 + lk2;
            #pragma unroll
            for (int j = 0; j < 8; j++) {
                const int nn = j * 8 + lr4;
                uint32_t bh[2], bl[2];
                bh[0] = *(const uint32_t*)(Kh + nn * FPAD + kb);
                bh[1] = *(const uint32_t*)(Kh + nn * FPAD + kb + 8);
                bl[0] = *(const uint32_t*)(Kl + nn * FPAD + kb);
                bl[1] = *(const uint32_t*)(Kl + nn * FPAD + kb + 8);
                mma16816(s[j], qh[st], bh);
                mma16816(s[j], qh[st], bl);
                mma16816(s[j], ql[st], bh);
            }
        }

        // ---- causal mask (only tiles that can cross the diagonal) ----
        if (kt >= 2 * qi) {
            const int r0g = q0 + w * 16 + lr4;
            const int r1g = r0g + 8;
            #pragma unroll
            for (int j = 0; j < 8; j++) {
                const int cg = kt * 64 + j * 8 + lk2;
                if (cg     > r0g) s[j][0] = -1e30f;
                if (cg + 1 > r0g) s[j][1] = -1e30f;
                if (cg     > r1g) s[j][2] = -1e30f;
                if (cg + 1 > r1g) s[j][3] = -1e30f;
            }
        }

        // ---- online softmax ----
        float mx0 = -1e30f, mx1 = -1e30f;
        #pragma unroll
        for (int j = 0; j < 8; j++) {
            mx0 = fmaxf(mx0, fmaxf(s[j][0], s[j][1]));
            mx1 = fmaxf(mx1, fmaxf(s[j][2], s[j][3]));
        }
        mx0 = fmaxf(mx0, __shfl_xor_sync(0xffffffffu, mx0, 1));
        mx0 = fmaxf(mx0, __shfl_xor_sync(0xffffffffu, mx0, 2));
        mx1 = fmaxf(mx1, __shfl_xor_sync(0xffffffffu, mx1, 1));
        mx1 = fmaxf(mx1, __shfl_xor_sync(0xffffffffu, mx1, 2));

        const float mn0 = fmaxf(rm0, mx0);
        const float mn1 = fmaxf(rm1, mx1);
        const float a0 = __expf(rm0 - mn0);
        const float a1 = __expf(rm1 - mn1);
        rm0 = mn0; rm1 = mn1;

        float sum0 = 0.0f, sum1 = 0.0f;
        #pragma unroll
        for (int j = 0; j < 8; j++) {
            s[j][0] = __expf(s[j][0] - mn0);
            s[j][1] = __expf(s[j][1] - mn0);
            s[j][2] = __expf(s[j][2] - mn1);
            s[j][3] = __expf(s[j][3] - mn1);
            sum0 += s[j][0] + s[j][1];
            sum1 += s[j][2] + s[j][3];
        }
        sum0 += __shfl_xor_sync(0xffffffffu, sum0, 1);
        sum0 += __shfl_xor_sync(0xffffffffu, sum0, 2);
        sum1 += __shfl_xor_sync(0xffffffffu, sum1, 1);
        sum1 += __shfl_xor_sync(0xffffffffu, sum1, 2);
        rl0 = rl0 * a0 + sum0;
        rl1 = rl1 * a1 + sum1;

        #pragma unroll
        for (int j = 0; j < 8; j++) {
            o[j][0] *= a0; o[j][1] *= a0;
            o[j][2] *= a1; o[j][3] *= a1;
        }

        // ---- O += P V (P from registers, split; V via ldmatrix.trans) ----
        #pragma unroll
        for (int st = 0; st < 4; st++) {
            uint32_t pah[4], pal[4];
            split2(s[2*st][0],   s[2*st][1],   pah[0], pal[0]);
            split2(s[2*st][2],   s[2*st][3],   pah[1], pal[1]);
            split2(s[2*st+1][0], s[2*st+1][1], pah[2], pal[2]);
            split2(s[2*st+1][2], s[2*st+1][3], pah[3], pal[3]);
            const int vrow = st * 16 + (lane & 15);
            #pragma unroll
            for (int j = 0; j < 8; j++) {
                uint32_t bh[2], bl[2];
                ldmx2t(smem_u32(Vh + vrow * FPAD + j * 8), bh);
                ldmx2t(smem_u32(Vl + vrow * FPAD + j * 8), bl);
                mma16816(o[j], pah, bh);
                mma16816(o[j], pah, bl);
                mma16816(o[j], pal, bh);
            }
        }
    }

    // ---- epilogue: normalize, split to bf16 hi/lo, write ----
    const float inv0 = 1.0f / rl0;
    const float inv1 = 1.0f / rl1;
    const int r0g = q0 + w * 16 + lr4;
    const size_t row0 = (size_t)(r0g * N_BATCH + n) * E_DIM;
    const size_t row1 = (size_t)((r0g + 8) * N_BATCH + n) * E_DIM;
    #pragma unroll
    for (int j = 0; j < 8; j++) {
        const int col = h * D_HEAD + j * 8 + lk2;
        uint32_t hh, ll;
        split2(o[j][0] * inv0, o[j][1] * inv0, hh, ll);
        *(uint32_t*)(ah + row0 + col) = hh;
        *(uint32_t*)(al + row0 + col) = ll;
        split2(o[j][2] * inv1, o[j][3] * inv1, hh, ll);
        *(uint32_t*)(ah + row1 + col) = hh;
        *(uint32_t*)(al + row1 + col) = ll;
    }
}

// ---------------------------------------------------------------------------
extern "C" void kernel_launch(void* const* d_in, const int* in_sizes, int n_in,
                              void* d_out, int out_size)
{
    const float* x     = (const float*)d_in[0];
    const float* w_qkv = (const float*)d_in[1];
    const float* w_out = (const float*)d_in[2];
    float* out = (float*)d_out;

    float *qkv;
    __nv_bfloat16 *xh, *xl, *wqh, *wql, *woh, *wol, *ah, *al;
    cudaGetSymbolAddress((void**)&qkv,  g_qkv);
    cudaGetSymbolAddress((void**)&xh,   g_xh);
    cudaGetSymbolAddress((void**)&xl,   g_xl);
    cudaGetSymbolAddress((void**)&wqh,  g_wqh);
    cudaGetSymbolAddress((void**)&wql,  g_wql);
    cudaGetSymbolAddress((void**)&woh,  g_woh);
    cudaGetSymbolAddress((void**)&wol,  g_wol);
    cudaGetSymbolAddress((void**)&ah,   g_ah);
    cudaGetSymbolAddress((void**)&al,   g_al);

    cudaFuncSetAttribute(gemm_mma,
                         cudaFuncAttributeMaxDynamicSharedMemorySize, GEMM_SMEM);

    // 0) split conversions of inputs
    {
        int n4 = ROWS_TOT * E_DIM / 4;
        convert_split<<<(n4 + 255) / 256, 256>>>(x, xh, xl, n4);
        n4 = F3 * E_DIM / 4;
        convert_split<<<(n4 + 255) / 256, 256>>>(w_qkv, wqh, wql, n4);
        n4 = E_DIM * E_DIM / 4;
        convert_split<<<(n4 + 255) / 256, 256>>>(w_out, woh, wol, n4);
    }

    // 1) QKV projection (tensor cores)
    gemm_mma<<<dim3(F3 / 128, ROWS_TOT / 128), 256, GEMM_SMEM>>>(
        xh, xl, wqh, wql, qkv, ROWS_TOT, F3, E_DIM);

    // 2) Causal flash attention (tensor cores); writes bf16 hi/lo split
    flash_mma<<<dim3(L_SEQ / 128, N_BATCH * H_HEADS), 256>>>(qkv, ah, al);

    // 3) Output projection (tensor cores)
    gemm_mma<<<dim3(E_DIM / 128, ROWS_TOT / 128), 256, GEMM_SMEM>>>(
        ah, al, woh, wol, out, ROWS_TOT, E_DIM, E_DIM);
}

// round 5
// speedup vs baseline: 2.5947x; 1.0717x over previous
#include <cuda_runtime.h>
#include <cuda_bf16.h>
#include <cstdint>
#include <cstddef>

// Problem constants
#define L_SEQ   2048
#define N_BATCH 2
#define E_DIM   1024
#define H_HEADS 16
#define D_HEAD  64
#define SCALE_F 0.125f
#define ROWS_TOT (L_SEQ * N_BATCH)     // 4096
#define F3       (3 * E_DIM)           // 3072
#define QKV_ROW  (N_BATCH * F3)        // 6144

// ---------------------------------------------------------------------------
// Scratch (no cudaMalloc allowed)
// ---------------------------------------------------------------------------
__device__ float g_qkv [(size_t)ROWS_TOT * F3];
__device__ __nv_bfloat16 g_xh [(size_t)ROWS_TOT * E_DIM];
__device__ __nv_bfloat16 g_xl [(size_t)ROWS_TOT * E_DIM];
__device__ __nv_bfloat16 g_wqh[(size_t)F3 * E_DIM];
__device__ __nv_bfloat16 g_wql[(size_t)F3 * E_DIM];
__device__ __nv_bfloat16 g_woh[(size_t)E_DIM * E_DIM];
__device__ __nv_bfloat16 g_wol[(size_t)E_DIM * E_DIM];
__device__ __nv_bfloat16 g_ah [(size_t)ROWS_TOT * E_DIM];
__device__ __nv_bfloat16 g_al [(size_t)ROWS_TOT * E_DIM];

// ---------------------------------------------------------------------------
// Helpers
// ---------------------------------------------------------------------------
__device__ __forceinline__ uint32_t smem_u32(const void* p) {
    uint32_t a;
    asm("{ .reg .u64 t; cvta.to.shared.u64 t, %1; cvt.u32.u64 %0, t; }"
        : "=r"(a) : "l"(p));
    return a;
}

__device__ __forceinline__ void cp_async16(uint32_t dst, const void* src) {
    asm volatile("cp.async.cg.shared.global [%0], [%1], 16;"
                 :: "r"(dst), "l"(src) : "memory");
}
#define CP_COMMIT()  asm volatile("cp.async.commit_group;" ::: "memory")
#define CP_WAIT(n)   asm volatile("cp.async.wait_group %0;" :: "n"(n) : "memory")

__device__ __forceinline__ void mma16816(float* d, const uint32_t* a,
                                         const uint32_t* b) {
    asm volatile(
        "mma.sync.aligned.m16n8k16.row.col.f32.bf16.bf16.f32 "
        "{%0,%1,%2,%3}, {%4,%5,%6,%7}, {%8,%9}, {%0,%1,%2,%3};"
        : "+f"(d[0]), "+f"(d[1]), "+f"(d[2]), "+f"(d[3])
        : "r"(a[0]), "r"(a[1]), "r"(a[2]), "r"(a[3]), "r"(b[0]), "r"(b[1]));
}

__device__ __forceinline__ void ldmx2t(uint32_t addr, uint32_t* r) {
    asm volatile("ldmatrix.sync.aligned.m8n8.x2.trans.shared.b16 {%0,%1}, [%2];"
                 : "=r"(r[0]), "=r"(r[1]) : "r"(addr));
}

// split a pair of fp32 into packed bf16 hi and bf16 lo (residual)
__device__ __forceinline__ void split2(float a, float b, uint32_t& hi, uint32_t& lo) {
    __nv_bfloat162 h = __floats2bfloat162_rn(a, b);
    float ra = a - __bfloat162float(h.x);
    float rb = b - __bfloat162float(h.y);
    __nv_bfloat162 l2 = __floats2bfloat162_rn(ra, rb);
    hi = *(uint32_t*)&h;
    lo = *(uint32_t*)&l2;
}

// ---------------------------------------------------------------------------
// Split conversion kernel (inputs)
// ---------------------------------------------------------------------------
__global__ void convert_split(const float* __restrict__ x,
                              __nv_bfloat16* __restrict__ hi,
                              __nv_bfloat16* __restrict__ lo, int n4)
{
    int i = blockIdx.x * blockDim.x + threadIdx.x;
    if (i >= n4) return;
    float4 v = *(const float4*)(x + (size_t)i * 4);
    uint32_t h0, l0, h1, l1;
    split2(v.x, v.y, h0, l0);
    split2(v.z, v.w, h1, l1);
    *(uint2*)(hi + (size_t)i * 4) = make_uint2(h0, h1);
    *(uint2*)(lo + (size_t)i * 4) = make_uint2(l0, l1);
}

// ---------------------------------------------------------------------------
// Split-bf16 NT GEMM on mma.sync: C[M][Nc] = A[M][K] * B[Nc][K]^T
// 128x128x32 CTA tile, 8 warps (2Mx4N), warp tile 64x32, 2-stage cp.async.
// Register-lean inner loop (B frags per-j) -> 2 CTAs/SM.
// ---------------------------------------------------------------------------
#define BK    32
#define PADK  40
#define TILE_BYTES  (128 * PADK * 2)
#define STAGE_BYTES (4 * TILE_BYTES)
#define GEMM_SMEM   (2 * STAGE_BYTES)

__global__ __launch_bounds__(256, 2) void gemm_mma(
    const __nv_bfloat16* __restrict__ Ah, const __nv_bfloat16* __restrict__ Al,
    const __nv_bfloat16* __restrict__ Bh, const __nv_bfloat16* __restrict__ Bl,
    float* __restrict__ C, int M, int Nc, int K)
{
    extern __shared__ __align__(16) char smem[];
    const int tid  = threadIdx.x;
    const int lane = tid & 31;
    const int wid  = tid >> 5;
    const int bm = blockIdx.y * 128;
    const int bn = blockIdx.x * 128;
    const int wm = (wid >> 2) * 64;
    const int wn = (wid & 3) * 32;

    const __nv_bfloat16* gsrc[4] = {
        Ah + (size_t)bm * K, Al + (size_t)bm * K,
        Bh + (size_t)bn * K, Bl + (size_t)bn * K };

    const int lrow = tid >> 2;
    const int lcb  = (tid & 3) * 8;

    auto load_stage = [&](int stage, int c) {
        const int k0 = c * BK;
        #pragma unroll
        for (int t = 0; t < 4; t++) {
            __nv_bfloat16* dst =
                (__nv_bfloat16*)(smem + stage * STAGE_BYTES + t * TILE_BYTES);
            #pragma unroll
            for (int it = 0; it < 2; it++) {
                const int r = lrow + it * 64;
                cp_async16(smem_u32(dst + r * PADK + lcb),
                           gsrc[t] + (size_t)r * K + k0 + lcb);
            }
        }
        CP_COMMIT();
    };

    float d[4][4][4];
    #pragma unroll
    for (int i = 0; i < 4; i++)
        #pragma unroll
        for (int j = 0; j < 4; j++)
            #pragma unroll
            for (int r = 0; r < 4; r++) d[i][j][r] = 0.0f;

    const int lr4 = lane >> 2;
    const int lk2 = (lane & 3) * 2;

    const int nch = K / BK;
    load_stage(0, 0);

    for (int c = 0; c < nch; c++) {
        const int sg = c & 1;
        if (c + 1 < nch) {
            load_stage((c + 1) & 1, c + 1);
            CP_WAIT(1);
        } else {
            CP_WAIT(0);
        }
        __syncthreads();

        const __nv_bfloat16* Ash =
            (const __nv_bfloat16*)(smem + sg * STAGE_BYTES);
        const __nv_bfloat16* Asl = Ash + 128 * PADK;
        const __nv_bfloat16* Bsh = Asl + 128 * PADK;
        const __nv_bfloat16* Bsl = Bsh + 128 * PADK;

        #pragma unroll
        for (int s = 0; s < 2; s++) {
            const int kb = s * 16 + lk2;
            uint32_t afh[4][4], afl[4][4];
            #pragma unroll
            for (int i = 0; i < 4; i++) {
                const int r = wm + i * 16 + lr4;
                afh[i][0] = *(const uint32_t*)(Ash + r * PADK + kb);
                afh[i][1] = *(const uint32_t*)(Ash + (r + 8) * PADK + kb);
                afh[i][2] = *(const uint32_t*)(Ash + r * PADK + kb + 8);
                afh[i][3] = *(const uint32_t*)(Ash + (r + 8) * PADK + kb + 8);
                afl[i][0] = *(const uint32_t*)(Asl + r * PADK + kb);
                afl[i][1] = *(const uint32_t*)(Asl + (r + 8) * PADK + kb);
                afl[i][2] = *(const uint32_t*)(Asl + r * PADK + kb + 8);
                afl[i][3] = *(const uint32_t*)(Asl + (r + 8) * PADK + kb + 8);
            }
            // B fragments loaded per-j: only 4 live B regs at a time.
            #pragma unroll
            for (int j = 0; j < 4; j++) {
                const int n = wn + j * 8 + lr4;
                uint32_t bfh[2], bfl[2];
                bfh[0] = *(const uint32_t*)(Bsh + n * PADK + kb);
                bfh[1] = *(const uint32_t*)(Bsh + n * PADK + kb + 8);
                bfl[0] = *(const uint32_t*)(Bsl + n * PADK + kb);
                bfl[1] = *(const uint32_t*)(Bsl + n * PADK + kb + 8);
                #pragma unroll
                for (int i = 0; i < 4; i++) {
                    mma16816(d[i][j], afh[i], bfh);
                    mma16816(d[i][j], afh[i], bfl);
                    mma16816(d[i][j], afl[i], bfh);
                }
            }
        }
        __syncthreads();
    }

    #pragma unroll
    for (int i = 0; i < 4; i++) {
        const int row = bm + wm + i * 16 + lr4;
        #pragma unroll
        for (int j = 0; j < 4; j++) {
            const int col = bn + wn + j * 8 + lk2;
            *(float2*)(C + (size_t)row * Nc + col) =
                make_float2(d[i][j][0], d[i][j][1]);
            *(float2*)(C + (size_t)(row + 8) * Nc + col) =
                make_float2(d[i][j][2], d[i][j][3]);
        }
    }
}

// ---------------------------------------------------------------------------
// Flash attention on mma.sync, split-bf16, causal — unchanged from R4.
// ---------------------------------------------------------------------------
#define FPAD 72

__global__ __launch_bounds__(256) void flash_mma(
    const float* __restrict__ qkv,
    __nv_bfloat16* __restrict__ ah, __nv_bfloat16* __restrict__ al)
{
    __shared__ __align__(16) char fsm[4 * 64 * FPAD * 2];
    float* Qst = (float*)fsm;
    __nv_bfloat16* Kh = (__nv_bfloat16*)fsm;
    __nv_bfloat16* Kl = Kh + 64 * FPAD;
    __nv_bfloat16* Vh = Kl + 64 * FPAD;
    __nv_bfloat16* Vl = Vh + 64 * FPAD;

    const int tid  = threadIdx.x;
    const int lane = tid & 31;
    const int w    = tid >> 5;
    const int qi   = (int)gridDim.x - 1 - (int)blockIdx.x;
    const int by   = blockIdx.y;
    const int n    = by >> 4;
    const int h    = by & 15;
    const int q0   = qi * 128;
    const int lr4  = lane >> 2;
    const int lk2  = (lane & 3) * 2;

    const float* qb  = qkv + (size_t)n * F3 + h * D_HEAD;
    const float* kbp = qb + E_DIM;
    const float* vbp = qb + 2 * E_DIM;

    #pragma unroll
    for (int i = 0; i < 8; i++) {
        int ch = tid + i * 256;
        int r  = ch >> 4;
        int c  = (ch & 15) * 4;
        float4 v = *(const float4*)(qb + (size_t)(q0 + r) * QKV_ROW + c);
        float* dst = Qst + r * 68 + c;
        dst[0] = v.x * SCALE_F; dst[1] = v.y * SCALE_F;
        dst[2] = v.z * SCALE_F; dst[3] = v.w * SCALE_F;
    }
    __syncthreads();

    uint32_t qh[4][4], ql[4][4];
    {
        const int rq = w * 16 + lr4;
        #pragma unroll
        for (int s = 0; s < 4; s++) {
            const int k0 = s * 16 + lk2;
            const float* r0p = Qst + rq * 68;
            const float* r1p = Qst + (rq + 8) * 68;
            split2(r0p[k0],     r0p[k0 + 1], qh[s][0], ql[s][0]);
            split2(r1p[k0],     r1p[k0 + 1], qh[s][1], ql[s][1]);
            split2(r0p[k0 + 8], r0p[k0 + 9], qh[s][2], ql[s][2]);
            split2(r1p[k0 + 8], r1p[k0 + 9], qh[s][3], ql[s][3]);
        }
    }

    float rm0 = -1e30f, rm1 = -1e30f, rl0 = 0.0f, rl1 = 0.0f;
    float o[8][4];
    #pragma unroll
    for (int j = 0; j < 8; j++)
        #pragma unroll
        for (int r = 0; r < 4; r++) o[j][r] = 0.0f;

    const int nkt = 2 * qi + 2;
    for (int kt = 0; kt < nkt; kt++) {
        __syncthreads();

        #pragma unroll
        for (int i = 0; i < 4; i++) {
            int ch = tid + i * 256;
            int r  = ch >> 4;
            int c  = (ch & 15) * 4;
            size_t go = (size_t)(kt * 64 + r) * QKV_ROW + c;
            float4 vk = *(const float4*)(kbp + go);
            float4 vv = *(const float4*)(vbp + go);
            uint32_t h0, l0u, h1, l1u;
            split2(vk.x, vk.y, h0, l0u); split2(vk.z, vk.w, h1, l1u);
            *(uint2*)(Kh + r * FPAD + c) = make_uint2(h0, h1);
            *(uint2*)(Kl + r * FPAD + c) = make_uint2(l0u, l1u);
            split2(vv.x, vv.y, h0, l0u); split2(vv.z, vv.w, h1, l1u);
            *(uint2*)(Vh + r * FPAD + c) = make_uint2(h0, h1);
            *(uint2*)(Vl + r * FPAD + c) = make_uint2(l0u, l1u);
        }
        __syncthreads();

        float s[8][4];
        #pragma unroll
        for (int j = 0; j < 8; j++)
            #pragma unroll
            for (int r = 0; r < 4; r++) s[j][r] = 0.0f;

        #pragma unroll
        for (int st = 0; st < 4; st++) {
            const int kb = st * 16 + lk2;
            #pragma unroll
            for (int j = 0; j < 8; j++) {
                const int nn = j * 8 + lr4;
                uint32_t bh[2], bl[2];
                bh[0] = *(const uint32_t*)(Kh + nn * FPAD + kb);
                bh[1] = *(const uint32_t*)(Kh + nn * FPAD + kb + 8);
                bl[0] = *(const uint32_t*)(Kl + nn * FPAD + kb);
                bl[1] = *(const uint32_t*)(Kl + nn * FPAD + kb + 8);
                mma16816(s[j], qh[st], bh);
                mma16816(s[j], qh[st], bl);
                mma16816(s[j], ql[st], bh);
            }
        }

        if (kt >= 2 * qi) {
            const int r0g = q0 + w * 16 + lr4;
            const int r1g = r0g + 8;
            #pragma unroll
            for (int j = 0; j < 8; j++) {
                const int cg = kt * 64 + j * 8 + lk2;
                if (cg     > r0g) s[j][0] = -1e30f;
                if (cg + 1 > r0g) s[j][1] = -1e30f;
                if (cg     > r1g) s[j][2] = -1e30f;
                if (cg + 1 > r1g) s[j][3] = -1e30f;
            }
        }

        float mx0 = -1e30f, mx1 = -1e30f;
        #pragma unroll
        for (int j = 0; j < 8; j++) {
            mx0 = fmaxf(mx0, fmaxf(s[j][0], s[j][1]));
            mx1 = fmaxf(mx1, fmaxf(s[j][2], s[j][3]));
        }
        mx0 = fmaxf(mx0, __shfl_xor_sync(0xffffffffu, mx0, 1));
        mx0 = fmaxf(mx0, __shfl_xor_sync(0xffffffffu, mx0, 2));
        mx1 = fmaxf(mx1, __shfl_xor_sync(0xffffffffu, mx1, 1));
        mx1 = fmaxf(mx1, __shfl_xor_sync(0xffffffffu, mx1, 2));

        const float mn0 = fmaxf(rm0, mx0);
        const float mn1 = fmaxf(rm1, mx1);
        const float a0 = __expf(rm0 - mn0);
        const float a1 = __expf(rm1 - mn1);
        rm0 = mn0; rm1 = mn1;

        float sum0 = 0.0f, sum1 = 0.0f;
        #pragma unroll
        for (int j = 0; j < 8; j++) {
            s[j][0] = __expf(s[j][0] - mn0);
            s[j][1] = __expf(s[j][1] - mn0);
            s[j][2] = __expf(s[j][2] - mn1);
            s[j][3] = __expf(s[j][3] - mn1);
            sum0 += s[j][0] + s[j][1];
            sum1 += s[j][2] + s[j][3];
        }
        sum0 += __shfl_xor_sync(0xffffffffu, sum0, 1);
        sum0 += __shfl_xor_sync(0xffffffffu, sum0, 2);
        sum1 += __shfl_xor_sync(0xffffffffu, sum1, 1);
        sum1 += __shfl_xor_sync(0xffffffffu, sum1, 2);
        rl0 = rl0 * a0 + sum0;
        rl1 = rl1 * a1 + sum1;

        #pragma unroll
        for (int j = 0; j < 8; j++) {
            o[j][0] *= a0; o[j][1] *= a0;
            o[j][2] *= a1; o[j][3] *= a1;
        }

        #pragma unroll
        for (int st = 0; st < 4; st++) {
            uint32_t pah[4], pal[4];
            split2(s[2*st][0],   s[2*st][1],   pah[0], pal[0]);
            split2(s[2*st][2],   s[2*st][3],   pah[1], pal[1]);
            split2(s[2*st+1][0], s[2*st+1][1], pah[2], pal[2]);
            split2(s[2*st+1][2], s[2*st+1][3], pah[3], pal[3]);
            const int vrow = st * 16 + (lane & 15);
            #pragma unroll
            for (int j = 0; j < 8; j++) {
                uint32_t bh[2], bl[2];
                ldmx2t(smem_u32(Vh + vrow * FPAD + j * 8), bh);
                ldmx2t(smem_u32(Vl + vrow * FPAD + j * 8), bl);
                mma16816(o[j], pah, bh);
                mma16816(o[j], pah, bl);
                mma16816(o[j], pal, bh);
            }
        }
    }

    const float inv0 = 1.0f / rl0;
    const float inv1 = 1.0f / rl1;
    const int r0g = q0 + w * 16 + lr4;
    const size_t row0 = (size_t)(r0g * N_BATCH + n) * E_DIM;
    const size_t row1 = (size_t)((r0g + 8) * N_BATCH + n) * E_DIM;
    #pragma unroll
    for (int j = 0; j < 8; j++) {
        const int col = h * D_HEAD + j * 8 + lk2;
        uint32_t hh, ll;
        split2(o[j][0] * inv0, o[j][1] * inv0, hh, ll);
        *(uint32_t*)(ah + row0 + col) = hh;
        *(uint32_t*)(al + row0 + col) = ll;
        split2(o[j][2] * inv1, o[j][3] * inv1, hh, ll);
        *(uint32_t*)(ah + row1 + col) = hh;
        *(uint32_t*)(al + row1 + col) = ll;
    }
}

// ---------------------------------------------------------------------------
extern "C" void kernel_launch(void* const* d_in, const int* in_sizes, int n_in,
                              void* d_out, int out_size)
{
    const float* x     = (const float*)d_in[0];
    const float* w_qkv = (const float*)d_in[1];
    const float* w_out = (const float*)d_in[2];
    float* out = (float*)d_out;

    float *qkv;
    __nv_bfloat16 *xh, *xl, *wqh, *wql, *woh, *wol, *ah, *al;
    cudaGetSymbolAddress((void**)&qkv,  g_qkv);
    cudaGetSymbolAddress((void**)&xh,   g_xh);
    cudaGetSymbolAddress((void**)&xl,   g_xl);
    cudaGetSymbolAddress((void**)&wqh,  g_wqh);
    cudaGetSymbolAddress((void**)&wql,  g_wql);
    cudaGetSymbolAddress((void**)&woh,  g_woh);
    cudaGetSymbolAddress((void**)&wol,  g_wol);
    cudaGetSymbolAddress((void**)&ah,   g_ah);
    cudaGetSymbolAddress((void**)&al,   g_al);

    cudaFuncSetAttribute(gemm_mma,
                         cudaFuncAttributeMaxDynamicSharedMemorySize, GEMM_SMEM);

    // 0) split conversions of inputs
    {
        int n4 = ROWS_TOT * E_DIM / 4;
        convert_split<<<(n4 + 255) / 256, 256>>>(x, xh, xl, n4);
        n4 = F3 * E_DIM / 4;
        convert_split<<<(n4 + 255) / 256, 256>>>(w_qkv, wqh, wql, n4);
        n4 = E_DIM * E_DIM / 4;
        convert_split<<<(n4 + 255) / 256, 256>>>(w_out, woh, wol, n4);
    }

    // 1) QKV projection (tensor cores)
    gemm_mma<<<dim3(F3 / 128, ROWS_TOT / 128), 256, GEMM_SMEM>>>(
        xh, xl, wqh, wql, qkv, ROWS_TOT, F3, E_DIM);

    // 2) Causal flash attention (tensor cores); writes bf16 hi/lo split
    flash_mma<<<dim3(L_SEQ / 128, N_BATCH * H_HEADS), 256>>>(qkv, ah, al);

    // 3) Output projection (tensor cores)
    gemm_mma<<<dim3(E_DIM / 128, ROWS_TOT / 128), 256, GEMM_SMEM>>>(
        ah, al, woh, wol, out, ROWS_TOT, E_DIM, E_DIM);
}

// round 6
// speedup vs baseline: 2.6778x; 1.0320x over previous
#include <cuda_runtime.h>
#include <cuda_bf16.h>
#include <cstdint>
#include <cstddef>

// Problem constants
#define L_SEQ   2048
#define N_BATCH 2
#define E_DIM   1024
#define H_HEADS 16
#define D_HEAD  64
#define SCALE_F 0.125f
#define ROWS_TOT (L_SEQ * N_BATCH)     // 4096
#define F3       (3 * E_DIM)           // 3072
#define QKV_ROW  (N_BATCH * F3)        // 6144

// ---------------------------------------------------------------------------
// Scratch (no cudaMalloc allowed)
// ---------------------------------------------------------------------------
__device__ float g_qkv [(size_t)ROWS_TOT * F3];
__device__ __nv_bfloat16 g_xh [(size_t)ROWS_TOT * E_DIM];
__device__ __nv_bfloat16 g_xl [(size_t)ROWS_TOT * E_DIM];
__device__ __nv_bfloat16 g_wqh[(size_t)F3 * E_DIM];
__device__ __nv_bfloat16 g_wql[(size_t)F3 * E_DIM];
__device__ __nv_bfloat16 g_woh[(size_t)E_DIM * E_DIM];
__device__ __nv_bfloat16 g_wol[(size_t)E_DIM * E_DIM];
__device__ __nv_bfloat16 g_ah [(size_t)ROWS_TOT * E_DIM];
__device__ __nv_bfloat16 g_al [(size_t)ROWS_TOT * E_DIM];

// ---------------------------------------------------------------------------
// Helpers
// ---------------------------------------------------------------------------
__device__ __forceinline__ uint32_t smem_u32(const void* p) {
    uint32_t a;
    asm("{ .reg .u64 t; cvta.to.shared.u64 t, %1; cvt.u32.u64 %0, t; }"
        : "=r"(a) : "l"(p));
    return a;
}

__device__ __forceinline__ void cp_async16(uint32_t dst, const void* src) {
    asm volatile("cp.async.cg.shared.global [%0], [%1], 16;"
                 :: "r"(dst), "l"(src) : "memory");
}
#define CP_COMMIT()  asm volatile("cp.async.commit_group;" ::: "memory")
#define CP_WAIT(n)   asm volatile("cp.async.wait_group %0;" :: "n"(n) : "memory")

__device__ __forceinline__ void mma16816(float* d, const uint32_t* a,
                                         const uint32_t* b) {
    asm volatile(
        "mma.sync.aligned.m16n8k16.row.col.f32.bf16.bf16.f32 "
        "{%0,%1,%2,%3}, {%4,%5,%6,%7}, {%8,%9}, {%0,%1,%2,%3};"
        : "+f"(d[0]), "+f"(d[1]), "+f"(d[2]), "+f"(d[3])
        : "r"(a[0]), "r"(a[1]), "r"(a[2]), "r"(a[3]), "r"(b[0]), "r"(b[1]));
}

__device__ __forceinline__ void ldmx4(uint32_t addr, uint32_t* r) {
    asm volatile("ldmatrix.sync.aligned.m8n8.x4.shared.b16 {%0,%1,%2,%3}, [%4];"
                 : "=r"(r[0]), "=r"(r[1]), "=r"(r[2]), "=r"(r[3]) : "r"(addr));
}
__device__ __forceinline__ void ldmx2(uint32_t addr, uint32_t* r) {
    asm volatile("ldmatrix.sync.aligned.m8n8.x2.shared.b16 {%0,%1}, [%2];"
                 : "=r"(r[0]), "=r"(r[1]) : "r"(addr));
}
__device__ __forceinline__ void ldmx2t(uint32_t addr, uint32_t* r) {
    asm volatile("ldmatrix.sync.aligned.m8n8.x2.trans.shared.b16 {%0,%1}, [%2];"
                 : "=r"(r[0]), "=r"(r[1]) : "r"(addr));
}

// split a pair of fp32 into packed bf16 hi and bf16 lo (residual)
__device__ __forceinline__ void split2(float a, float b, uint32_t& hi, uint32_t& lo) {
    __nv_bfloat162 h = __floats2bfloat162_rn(a, b);
    float ra = a - __bfloat162float(h.x);
    float rb = b - __bfloat162float(h.y);
    __nv_bfloat162 l2 = __floats2bfloat162_rn(ra, rb);
    hi = *(uint32_t*)&h;
    lo = *(uint32_t*)&l2;
}

// ---------------------------------------------------------------------------
// Split conversion kernel (inputs)
// ---------------------------------------------------------------------------
__global__ void convert_split(const float* __restrict__ x,
                              __nv_bfloat16* __restrict__ hi,
                              __nv_bfloat16* __restrict__ lo, int n4)
{
    int i = blockIdx.x * blockDim.x + threadIdx.x;
    if (i >= n4) return;
    float4 v = *(const float4*)(x + (size_t)i * 4);
    uint32_t h0, l0, h1, l1;
    split2(v.x, v.y, h0, l0);
    split2(v.z, v.w, h1, l1);
    *(uint2*)(hi + (size_t)i * 4) = make_uint2(h0, h1);
    *(uint2*)(lo + (size_t)i * 4) = make_uint2(l0, l1);
}

// ---------------------------------------------------------------------------
// Split-bf16 NT GEMM on mma.sync: C[M][Nc] = A[M][K] * B[Nc][K]^T
// 128x128x32 CTA tile, 8 warps (2Mx4N), warp tile 64x32, 2-stage cp.async.
// Fragment loads via ldmatrix (x4 for A, x2 for B).
// ---------------------------------------------------------------------------
#define BK    32
#define PADK  40                       // 80-byte row stride (16B multiple)
#define PADB  (PADK * 2)
#define TILE_BYTES  (128 * PADB)
#define STAGE_BYTES (4 * TILE_BYTES)
#define GEMM_SMEM   (2 * STAGE_BYTES)

__global__ __launch_bounds__(256, 2) void gemm_mma(
    const __nv_bfloat16* __restrict__ Ah, const __nv_bfloat16* __restrict__ Al,
    const __nv_bfloat16* __restrict__ Bh, const __nv_bfloat16* __restrict__ Bl,
    float* __restrict__ C, int M, int Nc, int K)
{
    extern __shared__ __align__(16) char smem[];
    const int tid  = threadIdx.x;
    const int lane = tid & 31;
    const int wid  = tid >> 5;
    const int bm = blockIdx.y * 128;
    const int bn = blockIdx.x * 128;
    const int wm = (wid >> 2) * 64;
    const int wn = (wid & 3) * 32;

    const __nv_bfloat16* gsrc[4] = {
        Ah + (size_t)bm * K, Al + (size_t)bm * K,
        Bh + (size_t)bn * K, Bl + (size_t)bn * K };

    const int lrow = tid >> 2;
    const int lcb  = (tid & 3) * 8;

    auto load_stage = [&](int stage, int c) {
        const int k0 = c * BK;
        #pragma unroll
        for (int t = 0; t < 4; t++) {
            __nv_bfloat16* dst =
                (__nv_bfloat16*)(smem + stage * STAGE_BYTES + t * TILE_BYTES);
            #pragma unroll
            for (int it = 0; it < 2; it++) {
                const int r = lrow + it * 64;
                cp_async16(smem_u32(dst + r * PADK + lcb),
                           gsrc[t] + (size_t)r * K + k0 + lcb);
            }
        }
        CP_COMMIT();
    };

    float d[4][4][4];
    #pragma unroll
    for (int i = 0; i < 4; i++)
        #pragma unroll
        for (int j = 0; j < 4; j++)
            #pragma unroll
            for (int r = 0; r < 4; r++) d[i][j][r] = 0.0f;

    const int lr4 = lane >> 2;
    const int lk2 = (lane & 3) * 2;

    const uint32_t sbase = smem_u32(smem);
    // ldmatrix lane->address components (bytes)
    const uint32_t a_off = (uint32_t)((wm + (lane & 15)) * PADB + ((lane >> 4) * 8) * 2);
    const uint32_t b_off = (uint32_t)((wn + (lane & 7)) * PADB + (((lane >> 3) & 1) * 8) * 2);

    const int nch = K / BK;
    load_stage(0, 0);

    for (int c = 0; c < nch; c++) {
        const int sg = c & 1;
        if (c + 1 < nch) {
            load_stage((c + 1) & 1, c + 1);
            CP_WAIT(1);
        } else {
            CP_WAIT(0);
        }
        __syncthreads();

        const uint32_t sAh = sbase + (uint32_t)(sg * STAGE_BYTES);
        const uint32_t sAl = sAh + TILE_BYTES;
        const uint32_t sBh = sAl + TILE_BYTES;
        const uint32_t sBl = sBh + TILE_BYTES;

        #pragma unroll
        for (int s = 0; s < 2; s++) {
            const uint32_t kof = (uint32_t)(s * 32);    // s*16 elems = 32 bytes
            uint32_t afh[4][4], afl[4][4];
            #pragma unroll
            for (int i = 0; i < 4; i++) {
                const uint32_t ao = a_off + (uint32_t)(i * 16 * PADB) + kof;
                ldmx4(sAh + ao, afh[i]);
                ldmx4(sAl + ao, afl[i]);
            }
            #pragma unroll
            for (int j = 0; j < 4; j++) {
                const uint32_t bo = b_off + (uint32_t)(j * 8 * PADB) + kof;
                uint32_t bfh[2], bfl[2];
                ldmx2(sBh + bo, bfh);
                ldmx2(sBl + bo, bfl);
                #pragma unroll
                for (int i = 0; i < 4; i++) {
                    mma16816(d[i][j], afh[i], bfh);
                    mma16816(d[i][j], afh[i], bfl);
                    mma16816(d[i][j], afl[i], bfh);
                }
            }
        }
        __syncthreads();
    }

    #pragma unroll
    for (int i = 0; i < 4; i++) {
        const int row = bm + wm + i * 16 + lr4;
        #pragma unroll
        for (int j = 0; j < 4; j++) {
            const int col = bn + wn + j * 8 + lk2;
            *(float2*)(C + (size_t)row * Nc + col) =
                make_float2(d[i][j][0], d[i][j][1]);
            *(float2*)(C + (size_t)(row + 8) * Nc + col) =
                make_float2(d[i][j][2], d[i][j][3]);
        }
    }
}

// ---------------------------------------------------------------------------
// Flash attention on mma.sync, split-bf16, causal — unchanged (validated).
// ---------------------------------------------------------------------------
#define FPAD 72

__global__ __launch_bounds__(256) void flash_mma(
    const float* __restrict__ qkv,
    __nv_bfloat16* __restrict__ ah, __nv_bfloat16* __restrict__ al)
{
    __shared__ __align__(16) char fsm[4 * 64 * FPAD * 2];
    float* Qst = (float*)fsm;
    __nv_bfloat16* Kh = (__nv_bfloat16*)fsm;
    __nv_bfloat16* Kl = Kh + 64 * FPAD;
    __nv_bfloat16* Vh = Kl + 64 * FPAD;
    __nv_bfloat16* Vl = Vh + 64 * FPAD;

    const int tid  = threadIdx.x;
    const int lane = tid & 31;
    const int w    = tid >> 5;
    const int qi   = (int)gridDim.x - 1 - (int)blockIdx.x;
    const int by   = blockIdx.y;
    const int n    = by >> 4;
    const int h    = by & 15;
    const int q0   = qi * 128;
    const int lr4  = lane >> 2;
    const int lk2  = (lane & 3) * 2;

    const float* qb  = qkv + (size_t)n * F3 + h * D_HEAD;
    const float* kbp = qb + E_DIM;
    const float* vbp = qb + 2 * E_DIM;

    #pragma unroll
    for (int i = 0; i < 8; i++) {
        int ch = tid + i * 256;
        int r  = ch >> 4;
        int c  = (ch & 15) * 4;
        float4 v = *(const float4*)(qb + (size_t)(q0 + r) * QKV_ROW + c);
        float* dst = Qst + r * 68 + c;
        dst[0] = v.x * SCALE_F; dst[1] = v.y * SCALE_F;
        dst[2] = v.z * SCALE_F; dst[3] = v.w * SCALE_F;
    }
    __syncthreads();

    uint32_t qh[4][4], ql[4][4];
    {
        const int rq = w * 16 + lr4;
        #pragma unroll
        for (int s = 0; s < 4; s++) {
            const int k0 = s * 16 + lk2;
            const float* r0p = Qst + rq * 68;
            const float* r1p = Qst + (rq + 8) * 68;
            split2(r0p[k0],     r0p[k0 + 1], qh[s][0], ql[s][0]);
            split2(r1p[k0],     r1p[k0 + 1], qh[s][1], ql[s][1]);
            split2(r0p[k0 + 8], r0p[k0 + 9], qh[s][2], ql[s][2]);
            split2(r1p[k0 + 8], r1p[k0 + 9], qh[s][3], ql[s][3]);
        }
    }

    float rm0 = -1e30f, rm1 = -1e30f, rl0 = 0.0f, rl1 = 0.0f;
    float o[8][4];
    #pragma unroll
    for (int j = 0; j < 8; j++)
        #pragma unroll
        for (int r = 0; r < 4; r++) o[j][r] = 0.0f;

    const int nkt = 2 * qi + 2;
    for (int kt = 0; kt < nkt; kt++) {
        __syncthreads();

        #pragma unroll
        for (int i = 0; i < 4; i++) {
            int ch = tid + i * 256;
            int r  = ch >> 4;
            int c  = (ch & 15) * 4;
            size_t go = (size_t)(kt * 64 + r) * QKV_ROW + c;
            float4 vk = *(const float4*)(kbp + go);
            float4 vv = *(const float4*)(vbp + go);
            uint32_t h0, l0u, h1, l1u;
            split2(vk.x, vk.y, h0, l0u); split2(vk.z, vk.w, h1, l1u);
            *(uint2*)(Kh + r * FPAD + c) = make_uint2(h0, h1);
            *(uint2*)(Kl + r * FPAD + c) = make_uint2(l0u, l1u);
            split2(vv.x, vv.y, h0, l0u); split2(vv.z, vv.w, h1, l1u);
            *(uint2*)(Vh + r * FPAD + c) = make_uint2(h0, h1);
            *(uint2*)(Vl + r * FPAD + c) = make_uint2(l0u, l1u);
        }
        __syncthreads();

        float s[8][4];
        #pragma unroll
        for (int j = 0; j < 8; j++)
            #pragma unroll
            for (int r = 0; r < 4; r++) s[j][r] = 0.0f;

        #pragma unroll
        for (int st = 0; st < 4; st++) {
            const int kb = st * 16 + lk2;
            #pragma unroll
            for (int j = 0; j < 8; j++) {
                const int nn = j * 8 + lr4;
                uint32_t bh[2], bl[2];
                bh[0] = *(const uint32_t*)(Kh + nn * FPAD + kb);
                bh[1] = *(const uint32_t*)(Kh + nn * FPAD + kb + 8);
                bl[0] = *(const uint32_t*)(Kl + nn * FPAD + kb);
                bl[1] = *(const uint32_t*)(Kl + nn * FPAD + kb + 8);
                mma16816(s[j], qh[st], bh);
                mma16816(s[j], qh[st], bl);
                mma16816(s[j], ql[st], bh);
            }
        }

        if (kt >= 2 * qi) {
            const int r0g = q0 + w * 16 + lr4;
            const int r1g = r0g + 8;
            #pragma unroll
            for (int j = 0; j < 8; j++) {
                const int cg = kt * 64 + j * 8 + lk2;
                if (cg     > r0g) s[j][0] = -1e30f;
                if (cg + 1 > r0g) s[j][1] = -1e30f;
                if (cg     > r1g) s[j][2] = -1e30f;
                if (cg + 1 > r1g) s[j][3] = -1e30f;
            }
        }

        float mx0 = -1e30f, mx1 = -1e30f;
        #pragma unroll
        for (int j = 0; j < 8; j++) {
            mx0 = fmaxf(mx0, fmaxf(s[j][0], s[j][1]));
            mx1 = fmaxf(mx1, fmaxf(s[j][2], s[j][3]));
        }
        mx0 = fmaxf(mx0, __shfl_xor_sync(0xffffffffu, mx0, 1));
        mx0 = fmaxf(mx0, __shfl_xor_sync(0xffffffffu, mx0, 2));
        mx1 = fmaxf(mx1, __shfl_xor_sync(0xffffffffu, mx1, 1));
        mx1 = fmaxf(mx1, __shfl_xor_sync(0xffffffffu, mx1, 2));

        const float mn0 = fmaxf(rm0, mx0);
        const float mn1 = fmaxf(rm1, mx1);
        const float a0 = __expf(rm0 - mn0);
        const float a1 = __expf(rm1 - mn1);
        rm0 = mn0; rm1 = mn1;

        float sum0 = 0.0f, sum1 = 0.0f;
        #pragma unroll
        for (int j = 0; j < 8; j++) {
            s[j][0] = __expf(s[j][0] - mn0);
            s[j][1] = __expf(s[j][1] - mn0);
            s[j][2] = __expf(s[j][2] - mn1);
            s[j][3] = __expf(s[j][3] - mn1);
            sum0 += s[j][0] + s[j][1];
            sum1 += s[j][2] + s[j][3];
        }
        sum0 += __shfl_xor_sync(0xffffffffu, sum0, 1);
        sum0 += __shfl_xor_sync(0xffffffffu, sum0, 2);
        sum1 += __shfl_xor_sync(0xffffffffu, sum1, 1);
        sum1 += __shfl_xor_sync(0xffffffffu, sum1, 2);
        rl0 = rl0 * a0 + sum0;
        rl1 = rl1 * a1 + sum1;

        #pragma unroll
        for (int j = 0; j < 8; j++) {
            o[j][0] *= a0; o[j][1] *= a0;
            o[j][2] *= a1; o[j][3] *= a1;
        }

        #pragma unroll
        for (int st = 0; st < 4; st++) {
            uint32_t pah[4], pal[4];
            split2(s[2*st][0],   s[2*st][1],   pah[0], pal[0]);
            split2(s[2*st][2],   s[2*st][3],   pah[1], pal[1]);
            split2(s[2*st+1][0], s[2*st+1][1], pah[2], pal[2]);
            split2(s[2*st+1][2], s[2*st+1][3], pah[3], pal[3]);
            const int vrow = st * 16 + (lane & 15);
            #pragma unroll
            for (int j = 0; j < 8; j++) {
                uint32_t bh[2], bl[2];
                ldmx2t(smem_u32(Vh + vrow * FPAD + j * 8), bh);
                ldmx2t(smem_u32(Vl + vrow * FPAD + j * 8), bl);
                mma16816(o[j], pah, bh);
                mma16816(o[j], pah, bl);
                mma16816(o[j], pal, bh);
            }
        }
    }

    const float inv0 = 1.0f / rl0;
    const float inv1 = 1.0f / rl1;
    const int r0g = q0 + w * 16 + lr4;
    const size_t row0 = (size_t)(r0g * N_BATCH + n) * E_DIM;
    const size_t row1 = (size_t)((r0g + 8) * N_BATCH + n) * E_DIM;
    #pragma unroll
    for (int j = 0; j < 8; j++) {
        const int col = h * D_HEAD + j * 8 + lk2;
        uint32_t hh, ll;
        split2(o[j][0] * inv0, o[j][1] * inv0, hh, ll);
        *(uint32_t*)(ah + row0 + col) = hh;
        *(uint32_t*)(al + row0 + col) = ll;
        split2(o[j][2] * inv1, o[j][3] * inv1, hh, ll);
        *(uint32_t*)(ah + row1 + col) = hh;
        *(uint32_t*)(al + row1 + col) = ll;
    }
}

// ---------------------------------------------------------------------------
extern "C" void kernel_launch(void* const* d_in, const int* in_sizes, int n_in,
                              void* d_out, int out_size)
{
    const float* x     = (const float*)d_in[0];
    const float* w_qkv = (const float*)d_in[1];
    const float* w_out = (const float*)d_in[2];
    float* out = (float*)d_out;

    float *qkv;
    __nv_bfloat16 *xh, *xl, *wqh, *wql, *woh, *wol, *ah, *al;
    cudaGetSymbolAddress((void**)&qkv,  g_qkv);
    cudaGetSymbolAddress((void**)&xh,   g_xh);
    cudaGetSymbolAddress((void**)&xl,   g_xl);
    cudaGetSymbolAddress((void**)&wqh,  g_wqh);
    cudaGetSymbolAddress((void**)&wql,  g_wql);
    cudaGetSymbolAddress((void**)&woh,  g_woh);
    cudaGetSymbolAddress((void**)&wol,  g_wol);
    cudaGetSymbolAddress((void**)&ah,   g_ah);
    cudaGetSymbolAddress((void**)&al,   g_al);

    cudaFuncSetAttribute(gemm_mma,
                         cudaFuncAttributeMaxDynamicSharedMemorySize, GEMM_SMEM);

    // 0) split conversions of inputs
    {
        int n4 = ROWS_TOT * E_DIM / 4;
        convert_split<<<(n4 + 255) / 256, 256>>>(x, xh, xl, n4);
        n4 = F3 * E_DIM / 4;
        convert_split<<<(n4 + 255) / 256, 256>>>(w_qkv, wqh, wql, n4);
        n4 = E_DIM * E_DIM / 4;
        convert_split<<<(n4 + 255) / 256, 256>>>(w_out, woh, wol, n4);
    }

    // 1) QKV projection (tensor cores)
    gemm_mma<<<dim3(F3 / 128, ROWS_TOT / 128), 256, GEMM_SMEM>>>(
        xh, xl, wqh, wql, qkv, ROWS_TOT, F3, E_DIM);

    // 2) Causal flash attention (tensor cores); writes bf16 hi/lo split
    flash_mma<<<dim3(L_SEQ / 128, N_BATCH * H_HEADS), 256>>>(qkv, ah, al);

    // 3) Output projection (tensor cores)
    gemm_mma<<<dim3(E_DIM / 128, ROWS_TOT / 128), 256, GEMM_SMEM>>>(
        ah, al, woh, wol, out, ROWS_TOT, E_DIM, E_DIM);
}